// round 17
// baseline (speedup 1.0000x reference)
#include <cuda_runtime.h>
#include <math.h>
#include <stdint.h>

// ---------------------------------------------------------------------------
// Problem constants
// ---------------------------------------------------------------------------
#define BB 128
#define CC 64
#define TT 500
#define NSIG (BB*CC)          // 8192
#define FEAT 16
#define GC 32
#define HH 4
#define NCLS 2

// xl layout strides (conflict-free LDS)
#define SJ 36
#define SH 2312
#define EST 65

// ---------------------------------------------------------------------------
// Device scratch
// ---------------------------------------------------------------------------
__device__ float g_xl1[NSIG * HH * GC];
__device__ float g_skip[NSIG * GC];
__device__ float g_sv1[NSIG * HH];
__device__ float g_dv1[NSIG * HH];
__device__ float g_sum1[GC];
__device__ float g_sum2[GC];
__device__ float g_pooled[BB * GC];
__device__ int    g_deg[CC];
__device__ float2 g_edges[CC * EST];
__device__ int    g_cnt1;
__device__ int    g_cnt2;

__device__ __forceinline__ float eluf(float v) {
    return v > 0.f ? v : (__expf(v) - 1.f);
}
__device__ __forceinline__ float geluf(float v) {
    return 0.5f * v * (1.f + erff(v * 0.70710678118654752f));
}

// ---- packed f32x2 helpers ----
typedef unsigned long long ull;
__device__ __forceinline__ ull pk2(float lo, float hi) {
    ull r;
    asm("mov.b64 %0, {%1, %2};" : "=l"(r) : "f"(lo), "f"(hi));
    return r;
}
__device__ __forceinline__ void upk2(ull v, float& lo, float& hi) {
    asm("mov.b64 {%0, %1}, %2;" : "=f"(lo), "=f"(hi) : "l"(v));
}
__device__ __forceinline__ ull fma2(ull a, ull b, ull c) {
    ull d;
    asm("fma.rn.f32x2 %0, %1, %2, %3;" : "=l"(d) : "l"(a), "l"(b), "l"(c));
    return d;
}

// ---------------------------------------------------------------------------
// Kernel 1: fused feature extractor + gat1 front-end + (block NSIG) graph build.
// ---------------------------------------------------------------------------
struct ExSmem {
    float sx[528];
    float A[16 * 502];
    float B[16 * 502];
    float2 w1p[200];
    float2 spwp[128];
    float2 bn1ps[8], bn1pb[8];
    float2 bn3ps[8], bn3pb[8];
    float dww[48];
    float sdww[48];
    float bn2s[16], bn2b[16];
    float red[8 * 16];
    float feat[16];
    float xlv[128];
};

extern __shared__ unsigned char smem_raw[];

__global__ __launch_bounds__(256) void extractor_kernel(
    const float* __restrict__ x,
    const float* __restrict__ conv1_w, const float* __restrict__ bn_c1,
    const float* __restrict__ dw_w,    const float* __restrict__ bn_c2,
    const float* __restrict__ sdw_w,   const float* __restrict__ spw_w,
    const float* __restrict__ bn_c3,
    const float* __restrict__ gat1w,   const float* __restrict__ asrc,
    const float* __restrict__ adst,    const float* __restrict__ skipw,
    const float* __restrict__ node_embed, const int* __restrict__ edges)
{
    const int tid = threadIdx.x;
    const int n = blockIdx.x;

    // ================= graph-builder block =================
    if (n == NSIG) {
        float* E      = reinterpret_cast<float*>(smem_raw);
        float* ee     = E + 1024;
        float* msm    = ee + 4096;
        float* rowsum = msm + 4096;

        if (tid < GC) { g_sum1[tid] = 0.f; g_sum2[tid] = 0.f; }
        if (tid == 0) { g_cnt1 = 0; g_cnt2 = 0; }

        for (int i = tid; i < CC * FEAT; i += 256) E[i] = node_embed[i];
        for (int i = tid; i < CC * CC; i += 256) msm[i] = 0.f;
        __syncthreads();

        for (int idx = tid; idx < CC * CC; idx += 256) {
            int i = idx >> 6, j = idx & 63;
            float v = 0.f;
            #pragma unroll
            for (int d = 0; d < FEAT; d++) v += E[i * FEAT + d] * E[j * FEAT + d];
            ee[idx] = v > 0.f ? v : 0.f;
        }
        __syncthreads();

        if (tid < CC) {
            float v = 0.f;
            #pragma unroll
            for (int j = 0; j < CC; j++) v += ee[tid * CC + j];
            rowsum[tid] = v;
        }
        {
            int e = tid;
            int src = edges[e], dst = edges[256 + e];
            atomicAdd(&msm[src * CC + dst], 1.0f);
        }
        __syncthreads();

        if (tid < CC) {
            const int i = tid;
            const float inv = 1.f / (rowsum[i] + 1e-6f);
            int d = 0;
            for (int j = 0; j < CC; j++) {
                float Mv;
                if (i == j) {
                    Mv = 1.f;
                } else {
                    float dyn = (ee[i * CC + j] * inv) > 0.1f ? 1.f : 0.f;
                    Mv = msm[i * CC + j] + dyn;
                }
                if (Mv > 0.f) {
                    g_edges[i * EST + d] = make_float2(__int_as_float(j), __logf(Mv));
                    d++;
                }
            }
            g_deg[i] = d;
            for (int k = d; k < EST; k++)
                g_edges[i * EST + k] = make_float2(__int_as_float(i), -1e30f);
        }
        return;
    }

    // ================= extractor blocks =================
    ExSmem* s = reinterpret_cast<ExSmem*>(smem_raw);

    for (int i = tid; i < 528; i += 256) {
        int t = i - 12;
        s->sx[i] = (t >= 0 && t < TT) ? x[n * TT + t] : 0.f;
    }
    {
        int i = tid;
        if (i < 200) {
            int k = i >> 3, cp = i & 7;
            s->w1p[i] = make_float2(conv1_w[(2 * cp) * 25 + k],
                                    conv1_w[(2 * cp + 1) * 25 + k]);
        }
    }
    if (tid < 128) {
        int c = tid >> 3, op = tid & 7;
        s->spwp[tid] = make_float2(spw_w[(2 * op) * 16 + c],
                                   spw_w[(2 * op + 1) * 16 + c]);
    }
    if (tid < 48) { s->dww[tid] = dw_w[tid]; s->sdww[tid] = sdw_w[tid]; }
    if (tid >= 208 && tid < 224) {
        int f = tid - 208;
        float g = bn_c2[f], b = bn_c2[16 + f], m = bn_c2[32 + f], v = bn_c2[48 + f];
        float sc = g * rsqrtf(v + 1e-5f);
        s->bn2s[f] = sc; s->bn2b[f] = b - m * sc;
    } else if (tid >= 224 && tid < 232) {
        int p = tid - 224;
        float sc0, sh0, sc1, sh1;
        {   int c = 2 * p;
            float g = bn_c1[c], b = bn_c1[16 + c], m = bn_c1[32 + c], v = bn_c1[48 + c];
            sc0 = g * rsqrtf(v + 1e-5f); sh0 = b - m * sc0; }
        {   int c = 2 * p + 1;
            float g = bn_c1[c], b = bn_c1[16 + c], m = bn_c1[32 + c], v = bn_c1[48 + c];
            sc1 = g * rsqrtf(v + 1e-5f); sh1 = b - m * sc1; }
        s->bn1ps[p] = make_float2(sc0, sc1); s->bn1pb[p] = make_float2(sh0, sh1);
    } else if (tid >= 232 && tid < 240) {
        int p = tid - 232;
        float sc0, sh0, sc1, sh1;
        {   int c = 2 * p;
            float g = bn_c3[c], b = bn_c3[16 + c], m = bn_c3[32 + c], v = bn_c3[48 + c];
            sc0 = g * rsqrtf(v + 1e-5f); sh0 = b - m * sc0; }
        {   int c = 2 * p + 1;
            float g = bn_c3[c], b = bn_c3[16 + c], m = bn_c3[32 + c], v = bn_c3[48 + c];
            sc1 = g * rsqrtf(v + 1e-5f); sh1 = b - m * sc1; }
        s->bn3ps[p] = make_float2(sc0, sc1); s->bn3pb[p] = make_float2(sh0, sh1);
    }
    {
        int q = tid - 144;
        if (q >= 0 && q < 64) {
            int half = q >> 5, r = q & 31;
            int c = r >> 1, side = r & 1;
            float* arr = half ? s->B : s->A;
            arr[c * 502 + side * 501] = 0.f;
        }
    }
    __syncthreads();

    const int g = tid & 127;
    const int cb = tid >> 7;

    // ---- conv1 (25-tap) + BN + ELU ----
    if (g < 125) {
        const int t0 = g << 2;
        float xv[28];
        const float4* sx4 = reinterpret_cast<const float4*>(s->sx);
        #pragma unroll
        for (int m = 0; m < 7; m++) {
            float4 v = sx4[(t0 >> 2) + m];
            xv[m * 4 + 0] = v.x; xv[m * 4 + 1] = v.y;
            xv[m * 4 + 2] = v.z; xv[m * 4 + 3] = v.w;
        }
        const ull* w1u = reinterpret_cast<const ull*>(s->w1p);
        const ull* bs  = reinterpret_cast<const ull*>(s->bn1ps);
        const ull* bb  = reinterpret_cast<const ull*>(s->bn1pb);
        #pragma unroll
        for (int pp = 0; pp < 2; pp++) {
            const int cp0 = (cb << 2) + pp * 2;
            const int cp1 = cp0 + 1;
            ull a0 = 0, a1 = 0, a2 = 0, a3 = 0;
            ull b0 = 0, b1 = 0, b2 = 0, b3 = 0;
            ull d0 = pk2(xv[0], xv[0]), d1 = pk2(xv[1], xv[1]);
            ull d2 = pk2(xv[2], xv[2]), d3 = pk2(xv[3], xv[3]);
            #pragma unroll
            for (int k = 0; k < 25; k++) {
                ull w0 = w1u[k * 8 + cp0];
                ull w1 = w1u[k * 8 + cp1];
                a0 = fma2(d0, w0, a0); a1 = fma2(d1, w0, a1);
                a2 = fma2(d2, w0, a2); a3 = fma2(d3, w0, a3);
                b0 = fma2(d0, w1, b0); b1 = fma2(d1, w1, b1);
                b2 = fma2(d2, w1, b2); b3 = fma2(d3, w1, b3);
                if (k < 24) {
                    d0 = d1; d1 = d2; d2 = d3;
                    d3 = pk2(xv[k + 4], xv[k + 4]);
                }
            }
            {
                ull sc = bs[cp0], sh = bb[cp0];
                a0 = fma2(a0, sc, sh); a1 = fma2(a1, sc, sh);
                a2 = fma2(a2, sc, sh); a3 = fma2(a3, sc, sh);
                float lo, hi;
                float* A0 = &s->A[(2 * cp0) * 502 + 1 + t0];
                float* A1 = &s->A[(2 * cp0 + 1) * 502 + 1 + t0];
                upk2(a0, lo, hi); A0[0] = eluf(lo); A1[0] = eluf(hi);
                upk2(a1, lo, hi); A0[1] = eluf(lo); A1[1] = eluf(hi);
                upk2(a2, lo, hi); A0[2] = eluf(lo); A1[2] = eluf(hi);
                upk2(a3, lo, hi); A0[3] = eluf(lo); A1[3] = eluf(hi);
            }
            {
                ull sc = bs[cp1], sh = bb[cp1];
                b0 = fma2(b0, sc, sh); b1 = fma2(b1, sc, sh);
                b2 = fma2(b2, sc, sh); b3 = fma2(b3, sc, sh);
                float lo, hi;
                float* A0 = &s->A[(2 * cp1) * 502 + 1 + t0];
                float* A1 = &s->A[(2 * cp1 + 1) * 502 + 1 + t0];
                upk2(b0, lo, hi); A0[0] = eluf(lo); A1[0] = eluf(hi);
                upk2(b1, lo, hi); A0[1] = eluf(lo); A1[1] = eluf(hi);
                upk2(b2, lo, hi); A0[2] = eluf(lo); A1[2] = eluf(hi);
                upk2(b3, lo, hi); A0[3] = eluf(lo); A1[3] = eluf(hi);
            }
        }
    }
    __syncthreads();

    // ---- depthwise 3-tap + BN + ELU ----
    if (g < 125) {
        const int t0 = g << 2;
        #pragma unroll
        for (int ci = 0; ci < 8; ci++) {
            const int c = cb * 8 + ci;
            const int base = c * 502 + t0;
            float2 a01 = *reinterpret_cast<const float2*>(&s->A[base]);
            float2 a23 = *reinterpret_cast<const float2*>(&s->A[base + 2]);
            float2 a45 = *reinterpret_cast<const float2*>(&s->A[base + 4]);
            float w0 = s->dww[c * 3], w1v = s->dww[c * 3 + 1], w2v = s->dww[c * 3 + 2];
            float sc = s->bn2s[c], sh = s->bn2b[c];
            float* Bp = &s->B[base + 1];
            Bp[0] = eluf((a01.x * w0 + a01.y * w1v + a23.x * w2v) * sc + sh);
            Bp[1] = eluf((a01.y * w0 + a23.x * w1v + a23.y * w2v) * sc + sh);
            Bp[2] = eluf((a23.x * w0 + a23.y * w1v + a45.x * w2v) * sc + sh);
            Bp[3] = eluf((a23.y * w0 + a45.x * w1v + a45.y * w2v) * sc + sh);
        }
    }
    __syncthreads();

    // ---- sdw(3-tap) -> pointwise 16x16 (f32x2) -> BN -> ELU -> sum ----
    float acc[16];
    #pragma unroll
    for (int o = 0; o < 16; o++) acc[o] = 0.f;
    if (tid < 250) {
        const int t0 = tid * 2;
        ull accA[8], accB[8];
        #pragma unroll
        for (int op = 0; op < 8; op++) { accA[op] = 0; accB[op] = 0; }
        const ull* spwu = reinterpret_cast<const ull*>(s->spwp);
        #pragma unroll
        for (int c = 0; c < 16; c++) {
            const int base = c * 502 + t0;
            float2 b01 = *reinterpret_cast<const float2*>(&s->B[base]);
            float2 b23 = *reinterpret_cast<const float2*>(&s->B[base + 2]);
            float w0 = s->sdww[c * 3], w1v = s->sdww[c * 3 + 1], w2v = s->sdww[c * 3 + 2];
            float sd0 = b01.x * w0 + b01.y * w1v + b23.x * w2v;
            float sd1 = b01.y * w0 + b23.x * w1v + b23.y * w2v;
            ull d0 = pk2(sd0, sd0), d1 = pk2(sd1, sd1);
            #pragma unroll
            for (int op = 0; op < 8; op++) {
                ull w = spwu[c * 8 + op];
                accA[op] = fma2(d0, w, accA[op]);
                accB[op] = fma2(d1, w, accB[op]);
            }
        }
        const ull* bs = reinterpret_cast<const ull*>(s->bn3ps);
        const ull* bb = reinterpret_cast<const ull*>(s->bn3pb);
        #pragma unroll
        for (int op = 0; op < 8; op++) {
            ull ya = fma2(accA[op], bs[op], bb[op]);
            ull yb = fma2(accB[op], bs[op], bb[op]);
            float a0, a1, c0, c1;
            upk2(ya, a0, a1); upk2(yb, c0, c1);
            acc[2 * op]     = eluf(a0) + eluf(c0);
            acc[2 * op + 1] = eluf(a1) + eluf(c1);
        }
    }
    int lane = tid & 31, warp = tid >> 5;
    #pragma unroll
    for (int o = 0; o < 16; o++) {
        float v = acc[o];
        #pragma unroll
        for (int off = 16; off > 0; off >>= 1) v += __shfl_xor_sync(0xffffffffu, v, off);
        if (lane == 0) s->red[warp * 16 + o] = v;
    }
    __syncthreads();
    if (tid < 16) {
        float v = 0.f;
        #pragma unroll
        for (int w = 0; w < 8; w++) v += s->red[w * 16 + tid];
        s->feat[tid] = v * (1.f / 500.f);
    }
    __syncthreads();

    if (tid < 128) {
        float a = 0.f;
        #pragma unroll
        for (int d = 0; d < FEAT; d++) a += s->feat[d] * __ldg(&gat1w[d * 128 + tid]);
        s->xlv[tid] = a;
        g_xl1[n * 128 + tid] = a;
    } else if (tid < 160) {
        const int f = tid - 128;
        float a = 0.f;
        #pragma unroll
        for (int d = 0; d < FEAT; d++) a += s->feat[d] * __ldg(&skipw[f * FEAT + d]);
        g_skip[n * GC + f] = a;
    }
    __syncthreads();
    if (tid < 8) {
        const int h = tid >> 1, which = tid & 1;
        const float* av = which ? adst : asrc;
        float a = 0.f;
        #pragma unroll
        for (int f2 = 0; f2 < GC; f2++) a += s->xlv[h * GC + f2] * __ldg(&av[h * GC + f2]);
        if (which) g_dv1[n * HH + h] = a;
        else       g_sv1[n * HH + h] = a;
    }
}

// ---------------------------------------------------------------------------
// Fused GAT1 + GAT2 + final: one persistent kernel, grid = BB (co-resident).
// ---------------------------------------------------------------------------
struct FGSmem {
    float xl[HH * SH];
    float xin[CC * GC];        // h1 lives here between phases
    float skip[CC * GC];
    float W[GC * HH * GC];
    float sv[CC * HH];
    float dv[CC * HH];
    float as2[HH * GC];
    float ad2[HH * GC];
    float bns1[GC], bnb1[GC], bias1[GC];
    float bns2[GC], bnb2[GC], bias2[GC];
    float sew1[8 * GC];
    float sew2[GC * 8];
    float gate[GC];
    float hid[8];
    float bsum[GC];
    float sbuf[256];
    float abuf[256 * 33];
    float2 earr[CC * EST];
    int   sdeg[CC];
};

__global__ __launch_bounds__(512) void fused_gat_kernel(
    const float* __restrict__ bias1g, const float* __restrict__ bng1,
    const float* __restrict__ Wg2,    const float* __restrict__ asrc2,
    const float* __restrict__ adst2,  const float* __restrict__ bias2g,
    const float* __restrict__ bng2,
    const float* __restrict__ se1w1, const float* __restrict__ se1w2,
    const float* __restrict__ se2w1, const float* __restrict__ se2w2,
    const float* __restrict__ clfw,  const float* __restrict__ clfb,
    float* __restrict__ out)
{
    FGSmem* s = reinterpret_cast<FGSmem*>(smem_raw);
    __shared__ int srank;
    const int tid = threadIdx.x;
    const int b = blockIdx.x;

    // ================= loads (everything, both phases) =================
    {
        const float4* src = reinterpret_cast<const float4*>(&g_xl1[b * CC * 128]);
        #pragma unroll
        for (int q = 0; q < 4; q++) {
            int idx4 = tid + q * 512;
            int idx = idx4 * 4;
            int j = idx >> 7, col = idx & 127;
            int h = col >> 5, f = col & 31;
            float4 v = src[idx4];
            *reinterpret_cast<float4*>(&s->xl[h * SH + j * SJ + f]) = v;
        }
    }
    if (tid < 256) {
        s->sv[tid] = g_sv1[b * 256 + tid];
        s->dv[tid] = g_dv1[b * 256 + tid];
    }
    {
        const float4* src = reinterpret_cast<const float4*>(&g_skip[b * CC * GC]);
        float4 v = src[tid];
        *reinterpret_cast<float4*>(&s->skip[tid * 4]) = v;
    }
    for (int i = tid; i < CC * EST; i += 512) s->earr[i] = g_edges[i];
    if (tid < CC) s->sdeg[tid] = g_deg[tid];
    for (int i = tid; i < 4096; i += 512) s->W[i] = Wg2[i];
    if (tid < 128) { s->as2[tid] = asrc2[tid]; s->ad2[tid] = adst2[tid]; }
    if (tid < 256) { s->sew1[tid] = se1w1[tid]; s->sew2[tid] = se1w2[tid]; }
    if (tid < GC) {
        {   float g = bng1[tid], bb2 = bng1[GC + tid], m = bng1[2 * GC + tid], v = bng1[3 * GC + tid];
            float sc = g * rsqrtf(v + 1e-5f);
            s->bns1[tid] = sc; s->bnb1[tid] = bb2 - m * sc;
            s->bias1[tid] = bias1g[tid]; }
        {   float g = bng2[tid], bb2 = bng2[GC + tid], m = bng2[2 * GC + tid], v = bng2[3 * GC + tid];
            float sc = g * rsqrtf(v + 1e-5f);
            s->bns2[tid] = sc; s->bnb2[tid] = bb2 - m * sc;
            s->bias2[tid] = bias2g[tid]; }
        s->bsum[tid] = 0.f;
    }
    __syncthreads();

    const int r = tid & 255;
    const int half = tid >> 8;
    const int i = r >> 2, h = r & 3;
    const int deg = s->sdeg[i];
    const float2* erow = &s->earr[i * EST];

    // ================= PHASE A: gat1 =================
    {
        const float di = s->dv[i * HH + h];
        float mx = -1e30f;
        for (int k = 0; k < deg; k++) {
            float2 e = erow[k];
            int j = __float_as_int(e.x);
            float l = di + s->sv[j * HH + h];
            l = l > 0.f ? l : 0.2f * l;
            l += e.y;
            mx = fmaxf(mx, l);
        }
        float acc[GC];
        #pragma unroll
        for (int f = 0; f < GC; f++) acc[f] = 0.f;
        float ssum = 0.f;
        for (int k = half; k < deg; k += 2) {
            float2 e = erow[k];
            int j = __float_as_int(e.x);
            float l = di + s->sv[j * HH + h];
            l = l > 0.f ? l : 0.2f * l;
            l += e.y;
            float w = __expf(l - mx);
            ssum += w;
            const float4* xp4 = reinterpret_cast<const float4*>(&s->xl[h * SH + j * SJ]);
            #pragma unroll
            for (int m = 0; m < 8; m++) {
                float4 v = xp4[m];
                acc[m * 4 + 0] += w * v.x; acc[m * 4 + 1] += w * v.y;
                acc[m * 4 + 2] += w * v.z; acc[m * 4 + 3] += w * v.w;
            }
        }
        if (half == 1) {
            #pragma unroll
            for (int f = 0; f < GC; f++) s->abuf[r * 33 + f] = acc[f];
            s->sbuf[r] = ssum;
        }
        __syncthreads();
        if (half == 0) {
            ssum += s->sbuf[r];
            #pragma unroll
            for (int f = 0; f < GC; f++) acc[f] += s->abuf[r * 33 + f];
            const float inv = 1.f / ssum;
            #pragma unroll
            for (int f = 0; f < GC; f++) {
                float v = acc[f] * inv;
                v += __shfl_xor_sync(0xffffffffu, v, 1);
                v += __shfl_xor_sync(0xffffffffu, v, 2);
                acc[f] = v * 0.25f;
            }
            if (h == 0) {
                float vals[GC];
                #pragma unroll
                for (int f = 0; f < GC; f++) {
                    float o = acc[f] + s->bias1[f];
                    o = o * s->bns1[f] + s->bnb1[f];
                    float val = geluf(o + s->skip[i * GC + f]);
                    s->xin[i * GC + f] = val;          // h1 stays in smem
                    vals[f] = val;
                }
                #pragma unroll
                for (int f = 0; f < GC; f++) {
                    float v = vals[f];
                    v += __shfl_xor_sync(0x11111111u, v, 4);
                    v += __shfl_xor_sync(0x11111111u, v, 8);
                    v += __shfl_xor_sync(0x11111111u, v, 16);
                    if ((tid & 31) == 0) atomicAdd(&s->bsum[f], v);
                }
            }
        }
        __syncthreads();
        if (tid < GC) atomicAdd(&g_sum1[tid], s->bsum[tid]);
    }

    // ================= grid barrier 1 =================
    __threadfence();
    __syncthreads();
    if (tid == 0) {
        atomicAdd(&g_cnt1, 1);
        while (((volatile int*)&g_cnt1)[0] < BB) { }
    }
    __syncthreads();
    __threadfence();
    if (tid < GC) s->bsum[tid] = 0.f;

    // ================= PHASE B: gat2 =================
    if (tid < 8) {
        const volatile float* vs1 = g_sum1;
        float a = 0.f;
        #pragma unroll
        for (int f = 0; f < GC; f++) a += (vs1[f] * (1.f / (float)NSIG)) * s->sew1[tid * GC + f];
        s->hid[tid] = a > 0.f ? a : 0.f;
    }
    __syncthreads();
    if (tid < GC) {
        float a = 0.f;
        #pragma unroll
        for (int k = 0; k < 8; k++) a += s->hid[k] * s->sew2[tid * 8 + k];
        s->gate[tid] = 1.f / (1.f + __expf(-a));
    }
    __syncthreads();
    for (int idx = tid; idx < CC * GC; idx += 512) s->xin[idx] *= s->gate[idx & 31];
    __syncthreads();

    {   // xl GEMM
        const int col = tid & 127;
        const int jg = tid >> 7;
        const int hh2 = col >> 5, f = col & 31;
        float wreg[GC];
        #pragma unroll
        for (int d = 0; d < GC; d++) wreg[d] = s->W[d * 128 + col];
        #pragma unroll
        for (int q = 0; q < 4; q++) {
            const int j0 = jg * 16 + q * 4;
            float a0 = 0.f, a1 = 0.f, a2 = 0.f, a3 = 0.f;
            #pragma unroll
            for (int dc = 0; dc < 8; dc++) {
                const float4 x0 = *reinterpret_cast<const float4*>(&s->xin[(j0 + 0) * GC + dc * 4]);
                const float4 x1 = *reinterpret_cast<const float4*>(&s->xin[(j0 + 1) * GC + dc * 4]);
                const float4 x2 = *reinterpret_cast<const float4*>(&s->xin[(j0 + 2) * GC + dc * 4]);
                const float4 x3 = *reinterpret_cast<const float4*>(&s->xin[(j0 + 3) * GC + dc * 4]);
                const float w0 = wreg[dc * 4], w1 = wreg[dc * 4 + 1];
                const float w2 = wreg[dc * 4 + 2], w3 = wreg[dc * 4 + 3];
                a0 += x0.x * w0 + x0.y * w1 + x0.z * w2 + x0.w * w3;
                a1 += x1.x * w0 + x1.y * w1 + x1.z * w2 + x1.w * w3;
                a2 += x2.x * w0 + x2.y * w1 + x2.z * w2 + x2.w * w3;
                a3 += x3.x * w0 + x3.y * w1 + x3.z * w2 + x3.w * w3;
            }
            s->xl[hh2 * SH + (j0 + 0) * SJ + f] = a0;
            s->xl[hh2 * SH + (j0 + 1) * SJ + f] = a1;
            s->xl[hh2 * SH + (j0 + 2) * SJ + f] = a2;
            s->xl[hh2 * SH + (j0 + 3) * SJ + f] = a3;
        }
    }
    __syncthreads();

    if (tid < 256) {
        int j = tid >> 2, hh2 = tid & 3;
        const float4* xp4 = reinterpret_cast<const float4*>(&s->xl[hh2 * SH + j * SJ]);
        const float4* as4 = reinterpret_cast<const float4*>(&s->as2[hh2 * GC]);
        const float4* ad4 = reinterpret_cast<const float4*>(&s->ad2[hh2 * GC]);
        float sa = 0.f, da = 0.f;
        #pragma unroll
        for (int m = 0; m < 8; m++) {
            float4 xv = xp4[m], av = as4[m], dvv = ad4[m];
            sa += xv.x * av.x + xv.y * av.y + xv.z * av.z + xv.w * av.w;
            da += xv.x * dvv.x + xv.y * dvv.y + xv.z * dvv.z + xv.w * dvv.w;
        }
        s->sv[j * HH + hh2] = sa;
        s->dv[j * HH + hh2] = da;
    }
    __syncthreads();

    {
        const float di = s->dv[i * HH + h];
        float mx = -1e30f;
        for (int k = 0; k < deg; k++) {
            float2 e = erow[k];
            int j = __float_as_int(e.x);
            float l = di + s->sv[j * HH + h];
            l = l > 0.f ? l : 0.2f * l;
            l += e.y;
            mx = fmaxf(mx, l);
        }
        float acc[GC];
        #pragma unroll
        for (int f = 0; f < GC; f++) acc[f] = 0.f;
        float ssum = 0.f;
        for (int k = half; k < deg; k += 2) {
            float2 e = erow[k];
            int j = __float_as_int(e.x);
            float l = di + s->sv[j * HH + h];
            l = l > 0.f ? l : 0.2f * l;
            l += e.y;
            float w = __expf(l - mx);
            ssum += w;
            const float4* xp4 = reinterpret_cast<const float4*>(&s->xl[h * SH + j * SJ]);
            #pragma unroll
            for (int m = 0; m < 8; m++) {
                float4 v = xp4[m];
                acc[m * 4 + 0] += w * v.x; acc[m * 4 + 1] += w * v.y;
                acc[m * 4 + 2] += w * v.z; acc[m * 4 + 3] += w * v.w;
            }
        }
        if (half == 1) {
            #pragma unroll
            for (int f = 0; f < GC; f++) s->abuf[r * 33 + f] = acc[f];
            s->sbuf[r] = ssum;
        }
        __syncthreads();
        if (half == 0) {
            ssum += s->sbuf[r];
            #pragma unroll
            for (int f = 0; f < GC; f++) acc[f] += s->abuf[r * 33 + f];
            const float inv = 1.f / ssum;
            #pragma unroll
            for (int f = 0; f < GC; f++) {
                float v = acc[f] * inv;
                v += __shfl_xor_sync(0xffffffffu, v, 1);
                v += __shfl_xor_sync(0xffffffffu, v, 2);
                acc[f] = v * 0.25f;
            }
            if (h == 0) {
                float vals[GC];
                #pragma unroll
                for (int f = 0; f < GC; f++) {
                    float o = acc[f] + s->bias2[f];
                    o = o * s->bns2[f] + s->bnb2[f];
                    vals[f] = geluf(o + s->xin[i * GC + f]);
                }
                #pragma unroll
                for (int f = 0; f < GC; f++) {
                    float v = vals[f];
                    v += __shfl_xor_sync(0x11111111u, v, 4);
                    v += __shfl_xor_sync(0x11111111u, v, 8);
                    v += __shfl_xor_sync(0x11111111u, v, 16);
                    if ((tid & 31) == 0) atomicAdd(&s->bsum[f], v);
                }
            }
        }
        __syncthreads();
        if (tid < GC) {
            atomicAdd(&g_sum2[tid], s->bsum[tid]);
            g_pooled[b * GC + tid] = s->bsum[tid] * (1.f / (float)CC);
        }
    }

    // ================= grid barrier 2 + final (last block) =================
    __threadfence();
    __syncthreads();
    if (tid == 0) srank = atomicAdd(&g_cnt2, 1);
    __syncthreads();
    if (srank == BB - 1) {
        __threadfence();
        if (tid < 8) {
            const volatile float* vs2 = g_sum2;
            float a = 0.f;
            #pragma unroll
            for (int f = 0; f < GC; f++) a += (vs2[f] * (1.f / (float)NSIG)) * se2w1[tid * GC + f];
            s->hid[tid] = a > 0.f ? a : 0.f;
        }
        __syncthreads();
        if (tid < GC) {
            float a = 0.f;
            #pragma unroll
            for (int k = 0; k < 8; k++) a += s->hid[k] * se2w2[tid * 8 + k];
            s->gate[tid] = 1.f / (1.f + __expf(-a));
        }
        __syncthreads();
        if (tid < 256) {
            int bb2 = tid >> 1, n2 = tid & 1;
            const volatile float* vp = g_pooled;
            float a = clfb[n2];
            #pragma unroll
            for (int f = 0; f < GC; f++)
                a += vp[bb2 * GC + f] * s->gate[f] * __ldg(&clfw[n2 * GC + f]);
            out[bb2 * NCLS + n2] = a;
        }
    }
}

// ---------------------------------------------------------------------------
// kernel_launch
// ---------------------------------------------------------------------------
extern "C" void kernel_launch(void* const* d_in, const int* in_sizes, int n_in,
                              void* d_out, int out_size)
{
    const float* x         = (const float*)d_in[0];
    const int*   edges     = (const int*)  d_in[1];
    const float* conv1_w   = (const float*)d_in[2];
    const float* bn_c1     = (const float*)d_in[3];
    const float* dw_w      = (const float*)d_in[4];
    const float* bn_c2     = (const float*)d_in[5];
    const float* sdw_w     = (const float*)d_in[6];
    const float* spw_w     = (const float*)d_in[7];
    const float* bn_c3     = (const float*)d_in[8];
    const float* node_emb  = (const float*)d_in[9];
    const float* gat1_w    = (const float*)d_in[10];
    const float* gat1_as   = (const float*)d_in[11];
    const float* gat1_ad   = (const float*)d_in[12];
    const float* gat1_b    = (const float*)d_in[13];
    const float* bn_g1     = (const float*)d_in[14];
    const float* skip1_w   = (const float*)d_in[15];
    const float* se1_w1    = (const float*)d_in[16];
    const float* se1_w2    = (const float*)d_in[17];
    const float* gat2_w    = (const float*)d_in[18];
    const float* gat2_as   = (const float*)d_in[19];
    const float* gat2_ad   = (const float*)d_in[20];
    const float* gat2_b    = (const float*)d_in[21];
    const float* bn_g2     = (const float*)d_in[22];
    const float* se2_w1    = (const float*)d_in[23];
    const float* se2_w2    = (const float*)d_in[24];
    const float* clf_w     = (const float*)d_in[25];
    const float* clf_b     = (const float*)d_in[26];
    float* out = (float*)d_out;

    cudaFuncSetAttribute(extractor_kernel, cudaFuncAttributeMaxDynamicSharedMemorySize, (int)sizeof(ExSmem));
    cudaFuncSetAttribute(fused_gat_kernel, cudaFuncAttributeMaxDynamicSharedMemorySize, (int)sizeof(FGSmem));

    extractor_kernel<<<NSIG + 1, 256, sizeof(ExSmem)>>>(x, conv1_w, bn_c1, dw_w, bn_c2,
                                                        sdw_w, spw_w, bn_c3,
                                                        gat1_w, gat1_as, gat1_ad, skip1_w,
                                                        node_emb, edges);
    fused_gat_kernel<<<BB, 512, sizeof(FGSmem)>>>(gat1_b, bn_g1,
                                                  gat2_w, gat2_as, gat2_ad, gat2_b, bn_g2,
                                                  se1_w1, se1_w2, se2_w1, se2_w2,
                                                  clf_w, clf_b, out);
}